// round 1
// baseline (speedup 1.0000x reference)
#include <cuda_runtime.h>
#include <math.h>

// Problem sizes (fixed by the reference)
#define BB 256
#define DD 512
#define HH 512

// Scratch: projections q,k,v,i,f,o  -> 6 * 256 * 512 * 4B = 3 MB
__device__ float g_proj[6][BB][HH];

struct GemmArgs {
    const float* x;        // [B, D] row-major
    const float* W[6];     // each [H, D] row-major (x @ W.T => dot of rows)
    const float* bias[3];  // b_i, b_f, b_o (for which = 3,4,5)
};

// Fused 6-way projection GEMM: M=256, N=3072 (6*512), K=512.
// BM=64, BN=64, BK=16, 256 threads, each thread computes a 4x4 micro-tile.
// Each 64-wide N tile lies entirely within one weight matrix (64 | 512).
__global__ __launch_bounds__(256) void proj_kernel(GemmArgs a) {
    const int BM = 64, BN = 64, BK = 16;
    __shared__ float As[BK][BM];   // A tile, transposed: As[k][m]
    __shared__ float Bs[BK][BN];   // B tile, transposed: Bs[k][n]

    const int n_tile = blockIdx.x;           // 0..47
    const int m_tile = blockIdx.y;           // 0..3
    const int which  = (n_tile * BN) / HH;   // which weight matrix
    const int h0     = (n_tile * BN) % HH;   // column offset within that matrix
    const int row0   = m_tile * BM;

    const float* __restrict__ W = a.W[which];
    const float* __restrict__ x = a.x;

    const int tid  = threadIdx.x;
    // Load mapping: 4 threads per row, each loads a float4 along K
    const int lrow = tid >> 2;         // 0..63
    const int lkq  = tid & 3;          // 0..3  (float4 index within BK=16)
    // Compute mapping: 16x16 thread grid of 4x4 micro-tiles
    const int tr = tid >> 4;           // 0..15 -> rows tr*4..tr*4+3
    const int tc = tid & 15;           // 0..15 -> cols tc*4..tc*4+3

    float acc[4][4];
#pragma unroll
    for (int i = 0; i < 4; i++)
#pragma unroll
        for (int j = 0; j < 4; j++) acc[i][j] = 0.0f;

    for (int k0 = 0; k0 < DD; k0 += BK) {
        // Load A tile: x[row0+lrow][k0 + lkq*4 .. +3]
        {
            const float4 va = *(const float4*)(x + (size_t)(row0 + lrow) * DD + k0 + lkq * 4);
            As[lkq * 4 + 0][lrow] = va.x;
            As[lkq * 4 + 1][lrow] = va.y;
            As[lkq * 4 + 2][lrow] = va.z;
            As[lkq * 4 + 3][lrow] = va.w;
        }
        // Load B tile: W[h0+lrow][k0 + lkq*4 .. +3]
        {
            const float4 vb = *(const float4*)(W + (size_t)(h0 + lrow) * DD + k0 + lkq * 4);
            Bs[lkq * 4 + 0][lrow] = vb.x;
            Bs[lkq * 4 + 1][lrow] = vb.y;
            Bs[lkq * 4 + 2][lrow] = vb.z;
            Bs[lkq * 4 + 3][lrow] = vb.w;
        }
        __syncthreads();

#pragma unroll
        for (int kk = 0; kk < BK; kk++) {
            const float4 av = *(const float4*)&As[kk][tr * 4];
            const float4 bv = *(const float4*)&Bs[kk][tc * 4];
            const float ar[4] = {av.x, av.y, av.z, av.w};
            const float br[4] = {bv.x, bv.y, bv.z, bv.w};
#pragma unroll
            for (int i = 0; i < 4; i++)
#pragma unroll
                for (int j = 0; j < 4; j++) acc[i][j] = fmaf(ar[i], br[j], acc[i][j]);
        }
        __syncthreads();
    }

    // Epilogue: optional bias + sigmoid for i/f/o, write to scratch
    const bool gate = (which >= 3);
    const float* __restrict__ bias = gate ? a.bias[which - 3] : nullptr;
#pragma unroll
    for (int i = 0; i < 4; i++) {
        const int r = row0 + tr * 4 + i;
#pragma unroll
        for (int j = 0; j < 4; j++) {
            const int h = h0 + tc * 4 + j;
            float v = acc[i][j];
            if (gate) {
                v += bias[h];
                v = 1.0f / (1.0f + __expf(-v));
            }
            g_proj[which][r][h] = v;
        }
    }
}

// Fused state update + readout.
// One warp per (b, i) row:
//   C_t[b,i,j] = f[b,i]*C_prev[b,i,j] + (i_t*k)[b,i]*v[b,j]
//   h_t[b,i]   = o[b,i] * tanh( sum_j C_t[b,i,j]*q[b,j] )
// Block: 512 threads = 16 warps -> 16 rows; grid (H/16, B).
__global__ __launch_bounds__(512) void update_kernel(const float* __restrict__ Cprev,
                                                     float* __restrict__ out_h,
                                                     float* __restrict__ out_C) {
    __shared__ float sv[HH];
    __shared__ float sq[HH];

    const int b   = blockIdx.y;
    const int i0  = blockIdx.x * 16;
    const int tid = threadIdx.x;

    // Stage v[b,:] and q[b,:] (shared across all 16 rows of this block)
    sv[tid] = g_proj[2][b][tid];
    sq[tid] = g_proj[0][b][tid];
    __syncthreads();

    const int warp = tid >> 5;
    const int lane = tid & 31;
    const int i    = i0 + warp;

    const float f_bi = g_proj[4][b][i];
    const float ik   = g_proj[3][b][i] * g_proj[1][b][i];
    const float o_bi = g_proj[5][b][i];

    const size_t rowoff = ((size_t)b * HH + i) * HH;
    const float4* __restrict__ Cp = (const float4*)(Cprev + rowoff);
    float4* __restrict__ Ct       = (float4*)(out_C + rowoff);
    const float4* __restrict__ v4 = (const float4*)sv;
    const float4* __restrict__ q4 = (const float4*)sq;

    float acc = 0.0f;
#pragma unroll
    for (int it = 0; it < 4; it++) {
        const int j4 = it * 32 + lane;    // 128 float4s per row
        float4 c = Cp[j4];
        const float4 vv = v4[j4];
        const float4 qq = q4[j4];
        c.x = fmaf(f_bi, c.x, ik * vv.x);
        c.y = fmaf(f_bi, c.y, ik * vv.y);
        c.z = fmaf(f_bi, c.z, ik * vv.z);
        c.w = fmaf(f_bi, c.w, ik * vv.w);
        Ct[j4] = c;
        acc += c.x * qq.x + c.y * qq.y + c.z * qq.z + c.w * qq.w;
    }

    // Warp reduction for the dot product
#pragma unroll
    for (int off = 16; off > 0; off >>= 1)
        acc += __shfl_xor_sync(0xFFFFFFFFu, acc, off);

    if (lane == 0) out_h[(size_t)b * HH + i] = o_bi * tanhf(acc);
}

extern "C" void kernel_launch(void* const* d_in, const int* in_sizes, int n_in,
                              void* d_out, int out_size) {
    // Inputs per metadata order:
    // 0:x 1:h_prev(unused) 2:C_prev 3:W_q 4:W_k 5:W_v 6:W_i 7:W_f 8:W_o 9:b_i 10:b_f 11:b_o
    const float* x     = (const float*)d_in[0];
    const float* Cprev = (const float*)d_in[2];

    GemmArgs a;
    a.x = x;
    a.W[0] = (const float*)d_in[3];  // W_q
    a.W[1] = (const float*)d_in[4];  // W_k
    a.W[2] = (const float*)d_in[5];  // W_v
    a.W[3] = (const float*)d_in[6];  // W_i
    a.W[4] = (const float*)d_in[7];  // W_f
    a.W[5] = (const float*)d_in[8];  // W_o
    a.bias[0] = (const float*)d_in[9];   // b_i
    a.bias[1] = (const float*)d_in[10];  // b_f
    a.bias[2] = (const float*)d_in[11];  // b_o

    float* out = (float*)d_out;
    float* out_h = out;                       // [B, H]
    float* out_C = out + (size_t)BB * HH;     // [B, H, H]

    dim3 gGemm(48, 4);            // N tiles (3072/64), M tiles (256/64)
    proj_kernel<<<gGemm, 256>>>(a);

    dim3 gUpd(HH / 16, BB);       // (32, 256) blocks, 512 threads
    update_kernel<<<gUpd, 512>>>(Cprev, out_h, out_C);
}